// round 12
// baseline (speedup 1.0000x reference)
#include <cuda_runtime.h>
#include <cuda_bf16.h>
#include <cstdint>

#define N_NODES 50000
#define KNB     10
#define VROWS   200000
#define FDIM    128
#define HDIM    64
#define GDIM    256   // 4*H

#define NBF ((VROWS   + 127) / 128)   // 1563 forward row blocks
#define NBT ((N_NODES + 127) / 128)   // 391  gather row blocks

typedef unsigned long long ull;

// scratch: projected forward table and backward gates (device globals — no allocs)
__device__ float g_P [(size_t)VROWS  * GDIM];   // 204.8 MB
__device__ float g_Gb[(size_t)N_NODES * GDIM];  //  51.2 MB

// ---------------- helpers ----------------
static __device__ __forceinline__ float sigm(float x) {
    return 1.0f / (1.0f + __expf(-x));
}
static __device__ __forceinline__ unsigned pack2bf(__nv_bfloat16 a, __nv_bfloat16 b) {
    __nv_bfloat162 t(a, b);
    return *(unsigned*)&t;
}
// warp-level bf16 HMMA (arch-portable; compiles under compute_103 virtual)
static __device__ __forceinline__ void mma16816(float* c,
    uint32_t a0, uint32_t a1, uint32_t a2, uint32_t a3, uint32_t b0, uint32_t b1) {
    asm volatile(
        "mma.sync.aligned.m16n8k16.row.col.f32.bf16.bf16.f32 "
        "{%0,%1,%2,%3}, {%4,%5,%6,%7}, {%8,%9}, {%0,%1,%2,%3};"
        : "+f"(c[0]), "+f"(c[1]), "+f"(c[2]), "+f"(c[3])
        : "r"(a0), "r"(a1), "r"(a2), "r"(a3), "r"(b0), "r"(b1));
}
static __device__ __forceinline__ void split_bf(float f, __nv_bfloat16& h, __nv_bfloat16& l) {
    h = __float2bfloat16_rn(f);
    l = __float2bfloat16_rn(f - __bfloat162float(h));
}

// ============================================================================
// Merged HMMA projection (both jobs in one launch):
//   blockIdx.y <  NBF : out = g_P,  rows = table rows,       W = Wih_f
//   blockIdx.y >= NBF : out = g_Gb, rows = E[idx[n][K-1]],   W = Wih_b
// out[row, gbase+g] = sum_f src[row][f] * W[g][f] + b1[g]+b2[g]
// fp32 via 3-term bf16 split: Ah*Bh + Ah*Bl + Al*Bh (fp32 accumulators).
// CTA tile: 128 rows x 64 gates, K=128 (smem 105 KB -> 2 CTAs/SM).
// grid.x = gate quarter (fast axis) -> concurrent blocks share A via L2.
// ============================================================================
#define ROW_U32 68          // 64 data u32 (128 bf16) + 4 pad -> (4g+t) conflict-free
#define TILE_A (128 * ROW_U32 * 4)          // 34816
#define TILE_B (64  * ROW_U32 * 4)          // 17408
#define OFF_IDX  0          // 128 ints
#define OFF_BIAS 512        // 64 floats
#define OFF_AH   1024
#define OFF_AL   (OFF_AH + TILE_A)          // 35840
#define OFF_BH   (OFF_AL + TILE_A)          // 70656
#define OFF_BL   (OFF_BH + TILE_B)          // 88064
#define TC_SMEM  (OFF_BL + TILE_B)          // 105472

__global__ __launch_bounds__(256, 2) void proj_all(
    const float* __restrict__ E,
    const float* __restrict__ Wf, const float* __restrict__ bf1, const float* __restrict__ bf2,
    const float* __restrict__ Wb, const float* __restrict__ bb1, const float* __restrict__ bb2,
    const int* __restrict__ nidx)
{
    extern __shared__ __align__(16) char smem[];
    int*      idxs = (int*)(smem + OFF_IDX);
    float*    bias = (float*)(smem + OFF_BIAS);
    uint32_t* Ah   = (uint32_t*)(smem + OFF_AH);
    uint32_t* Al   = (uint32_t*)(smem + OFF_AL);
    uint32_t* Bh   = (uint32_t*)(smem + OFF_BH);
    uint32_t* Bl   = (uint32_t*)(smem + OFF_BL);

    const int  tid    = threadIdx.x;
    const bool gather = (blockIdx.y >= NBF);
    const int  r0     = (gather ? (blockIdx.y - NBF) : blockIdx.y) * 128;
    const int  gbase  = blockIdx.x * 64;
    const int  nrows  = gather ? N_NODES : VROWS;
    const float* W  = gather ? Wb  : Wf;
    const float* b1 = gather ? bb1 : bf1;
    const float* b2 = gather ? bb2 : bf2;

    if (tid < 64) bias[tid] = b1[gbase + tid] + b2[gbase + tid];
    if (gather && tid < 128) {
        int n = r0 + tid; if (n >= nrows) n = nrows - 1;
        idxs[tid] = nidx[n * KNB + (KNB - 1)];
    }
    __syncthreads();

    // ---- fill B (weights, 64 gates x 128 k) hi/lo ----
    for (int u = tid; u < 64 * 16; u += 256) {
        int g = u >> 4, c8 = (u & 15) * 8;
        const float* src = W + (size_t)(gbase + g) * FDIM + c8;
        float4 v0 = *(const float4*)(src);
        float4 v1 = *(const float4*)(src + 4);
        float f[8] = {v0.x, v0.y, v0.z, v0.w, v1.x, v1.y, v1.z, v1.w};
        __nv_bfloat16 h[8], l[8];
        #pragma unroll
        for (int i = 0; i < 8; ++i) split_bf(f[i], h[i], l[i]);
        int du = g * ROW_U32 + (c8 >> 1);
        *(uint4*)&Bh[du] = make_uint4(pack2bf(h[0],h[1]), pack2bf(h[2],h[3]), pack2bf(h[4],h[5]), pack2bf(h[6],h[7]));
        *(uint4*)&Bl[du] = make_uint4(pack2bf(l[0],l[1]), pack2bf(l[2],l[3]), pack2bf(l[4],l[5]), pack2bf(l[6],l[7]));
    }
    // ---- fill A (rows, 128 x 128 k) hi/lo ----
    for (int u = tid; u < 128 * 16; u += 256) {
        int r = u >> 4, c8 = (u & 15) * 8;
        size_t srow;
        if (gather) srow = (size_t)idxs[r];
        else { int rr = r0 + r; if (rr >= nrows) rr = nrows - 1; srow = (size_t)rr; }
        const float* src = E + srow * FDIM + c8;
        float4 v0 = *(const float4*)(src);
        float4 v1 = *(const float4*)(src + 4);
        float f[8] = {v0.x, v0.y, v0.z, v0.w, v1.x, v1.y, v1.z, v1.w};
        __nv_bfloat16 h[8], l[8];
        #pragma unroll
        for (int i = 0; i < 8; ++i) split_bf(f[i], h[i], l[i]);
        int du = r * ROW_U32 + (c8 >> 1);
        *(uint4*)&Ah[du] = make_uint4(pack2bf(h[0],h[1]), pack2bf(h[2],h[3]), pack2bf(h[4],h[5]), pack2bf(h[6],h[7]));
        *(uint4*)&Al[du] = make_uint4(pack2bf(l[0],l[1]), pack2bf(l[2],l[3]), pack2bf(l[4],l[5]), pack2bf(l[6],l[7]));
    }
    __syncthreads();

    // ---- warp-tiled MMA: warp (wm, wn) owns rows wm*32..+31, gates wn*32..+31 ----
    const int wid  = tid >> 5, lane = tid & 31;
    const int wm   = wid & 3, wn = wid >> 2;
    const int g    = lane >> 2, t = lane & 3;

    float c[2][4][4];
    #pragma unroll
    for (int mi = 0; mi < 2; ++mi)
        #pragma unroll
        for (int ni = 0; ni < 4; ++ni)
            #pragma unroll
            for (int q = 0; q < 4; ++q) c[mi][ni][q] = 0.f;

    const uint32_t* Abase[3] = {Ah, Ah, Al};
    const uint32_t* Bbase[3] = {Bh, Bl, Bh};
    #pragma unroll
    for (int term = 0; term < 3; ++term) {
        const uint32_t* As = Abase[term];
        const uint32_t* Bs = Bbase[term];
        #pragma unroll
        for (int ks = 0; ks < 8; ++ks) {
            const int kc = ks * 8;
            uint32_t a[2][4];
            #pragma unroll
            for (int mi = 0; mi < 2; ++mi) {
                const uint32_t* ar = As + (wm * 32 + mi * 16 + g) * ROW_U32;
                a[mi][0] = ar[kc + t];
                a[mi][1] = ar[8 * ROW_U32 + kc + t];
                a[mi][2] = ar[kc + 4 + t];
                a[mi][3] = ar[8 * ROW_U32 + kc + 4 + t];
            }
            #pragma unroll
            for (int ni = 0; ni < 4; ++ni) {
                const uint32_t* br = Bs + (wn * 32 + ni * 8 + g) * ROW_U32;
                uint32_t b0 = br[kc + t];
                uint32_t b1 = br[kc + 4 + t];
                mma16816(c[0][ni], a[0][0], a[0][1], a[0][2], a[0][3], b0, b1);
                mma16816(c[1][ni], a[1][0], a[1][1], a[1][2], a[1][3], b0, b1);
            }
        }
    }

    // ---- bias + store ----
    float* outp = gather ? g_Gb : g_P;
    #pragma unroll
    for (int mi = 0; mi < 2; ++mi) {
        int row0 = r0 + wm * 32 + mi * 16 + g;
        #pragma unroll
        for (int ni = 0; ni < 4; ++ni) {
            int lc  = wn * 32 + ni * 8 + 2 * t;
            float bx = bias[lc], by = bias[lc + 1];
            if (row0 < nrows)
                *(float2*)&outp[(size_t)row0 * GDIM + gbase + lc] =
                    make_float2(c[mi][ni][0] + bx, c[mi][ni][1] + by);
            if (row0 + 8 < nrows)
                *(float2*)&outp[(size_t)(row0 + 8) * GDIM + gbase + lc] =
                    make_float2(c[mi][ni][2] + bx, c[mi][ni][3] + by);
        }
    }
}

// ============================================================================
// HMMA recurrence kernel: 32 nodes/block, 256 threads (8 warps).
// Conflict-free smem: Whh and H stored as stride-68 rows [hi 32 u32][lo 32][pad]
// -> every fragment LDS has bank (4g+t), no conflicts.
// Full-step gather prefetch: step k+1's g_P rows issued in two halves
// (q0..3 after MMA(k), q4..7 at end of cell(k)) -> ~1.5k cycles cover each.
// MMA staging split in two ni-halves keeps live regs ~119 (no spill at 128).
// smem 112.9 KB -> 2 CTAs/SM.
// ============================================================================
#define LNB 32
#define WST 68                  // u32 row stride: hi[0..31] lo[32..63] pad 4
#define GST 260                 // f32 row stride for gs
#define L_W  0                              // 256*68 = 17408 u32
#define L_H  (L_W + 256 * WST)              // 32*68  = 2176 u32
#define L_GS (L_H + LNB * WST)              // 32*260 = 8320 u32
#define L_IX (L_GS + LNB * GST)             // 320 u32
#define LSTM_SMEM ((L_IX + LNB * KNB) * 4)  // 112896 bytes

__global__ __launch_bounds__(256, 2) void lstm_kernel(
    const int* __restrict__ nidx, const float* __restrict__ Whh,
    float* __restrict__ out)
{
    extern __shared__ __align__(16) char smraw[];
    uint32_t* sm   = (uint32_t*)smraw;
    uint32_t* Ws   = sm + L_W;
    uint32_t* Hs   = sm + L_H;
    float*    gs   = (float*)(sm + L_GS);
    int*      idxs = (int*)(sm + L_IX);

    const int tid  = threadIdx.x;
    const int wid  = tid >> 5, lane = tid & 31;
    const int n0   = blockIdx.x * LNB;

    // ---- prologue: indices (grid-stride: 320 entries > 256 threads) ----
    for (int u = tid; u < LNB * KNB; u += 256) {
        int m = u / KNB, kk = u % KNB;
        int n = n0 + m; if (n >= N_NODES) n = N_NODES - 1;
        idxs[m * KNB + kk] = nidx[n * KNB + kk];
    }
    // ---- Whh hi/lo split into stride-68 rows (thread = gate row) ----
    {
        const float* wr = Whh + tid * HDIM;
        uint32_t* wrow = Ws + tid * WST;
        #pragma unroll
        for (int i = 0; i < 16; ++i) {
            float4 v = *(const float4*)(wr + i * 4);
            __nv_bfloat16 h0,l0,h1,l1,h2,l2,h3,l3;
            split_bf(v.x,h0,l0); split_bf(v.y,h1,l1);
            split_bf(v.z,h2,l2); split_bf(v.w,h3,l3);
            *(uint2*)&wrow[2*i]      = make_uint2(pack2bf(h0,h1), pack2bf(h2,h3));
            *(uint2*)&wrow[32 + 2*i] = make_uint2(pack2bf(l0,l1), pack2bf(l2,l3));
        }
    }
    __syncthreads();

    // cell-phase identity
    const int j    = tid & 63;
    const int msub = tid >> 6;
    float cst[8];
    #pragma unroll
    for (int q = 0; q < 8; ++q) cst[q] = 0.f;

    // gather buffers: F = nodes q0..3, S = nodes q4..7, N = next-step q0..3
    float xgF[4][4], xgS[4][4], xgN[4][4];
    #pragma unroll
    for (int q = 0; q < 4; ++q) {
        const float* xpF = g_P + (size_t)idxs[(msub * 8 + q)     * KNB + 0] * GDIM + j;
        const float* xpS = g_P + (size_t)idxs[(msub * 8 + q + 4) * KNB + 0] * GDIM + j;
        xgF[q][0] = xpF[0]; xgF[q][1] = xpF[64]; xgF[q][2] = xpF[128]; xgF[q][3] = xpF[192];
        xgS[q][0] = xpS[0]; xgS[q][1] = xpS[64]; xgS[q][2] = xpS[128]; xgS[q][3] = xpS[192];
    }

    #pragma unroll
    for (int k = 0; k < KNB; ++k) {
        // ---- MMA phase: R = H @ Whh^T (3-term split), skip at k=0 ----
        if (k > 0) {
            const int wm = wid >> 2, wn = wid & 3;   // wm 0..1 (16 rows), wn 0..3 (64 gates)
            const int g = lane >> 2, t = lane & 3;

            uint32_t ah[4][4], al[4][4];
            const uint32_t* ar = Hs + (wm * 16 + g) * WST;
            #pragma unroll
            for (int ks = 0; ks < 4; ++ks) {
                const int kc = ks * 8;
                ah[ks][0] = ar[kc + t];             ah[ks][1] = ar[8 * WST + kc + t];
                ah[ks][2] = ar[kc + 4 + t];         ah[ks][3] = ar[8 * WST + kc + 4 + t];
                al[ks][0] = ar[32 + kc + t];        al[ks][1] = ar[8 * WST + 32 + kc + t];
                al[ks][2] = ar[32 + kc + 4 + t];    al[ks][3] = ar[8 * WST + 32 + kc + 4 + t];
            }
            #pragma unroll
            for (int half = 0; half < 2; ++half) {
                float acc[4][4];
                #pragma unroll
                for (int ni = 0; ni < 4; ++ni)
                    #pragma unroll
                    for (int q = 0; q < 4; ++q) acc[ni][q] = 0.f;
                #pragma unroll
                for (int ni = 0; ni < 4; ++ni) {
                    const uint32_t* br = Ws + (wn * 64 + (half * 4 + ni) * 8 + g) * WST;
                    #pragma unroll
                    for (int ks = 0; ks < 4; ++ks) {
                        const int kc = ks * 8;
                        uint32_t bh0 = br[kc + t],      bh1 = br[kc + 4 + t];
                        uint32_t bl0 = br[32 + kc + t], bl1 = br[32 + kc + 4 + t];
                        mma16816(acc[ni], ah[ks][0], ah[ks][1], ah[ks][2], ah[ks][3], bh0, bh1);
                        mma16816(acc[ni], ah[ks][0], ah[ks][1], ah[ks][2], ah[ks][3], bl0, bl1);
                        mma16816(acc[ni], al[ks][0], al[ks][1], al[ks][2], al[ks][3], bh0, bh1);
                    }
                }
                const int r0w = wm * 16 + g;
                #pragma unroll
                for (int ni = 0; ni < 4; ++ni) {
                    int col = wn * 64 + (half * 4 + ni) * 8 + 2 * t;
                    *(float2*)&gs[r0w * GST + col]       = make_float2(acc[ni][0], acc[ni][1]);
                    *(float2*)&gs[(r0w + 8) * GST + col] = make_float2(acc[ni][2], acc[ni][3]);
                }
            }
        }

        // ---- prefetch next step, first half (covered by barrier + cell) ----
        if (k < KNB - 1) {
            #pragma unroll
            for (int q = 0; q < 4; ++q) {
                const float* xp = g_P + (size_t)idxs[(msub * 8 + q) * KNB + k + 1] * GDIM + j;
                xgN[q][0] = xp[0]; xgN[q][1] = xp[64]; xgN[q][2] = xp[128]; xgN[q][3] = xp[192];
            }
        }
        __syncthreads();

        // ---- cell phase: thread (j, msub) owns nodes m = msub*8+q ----
        #pragma unroll
        for (int q = 0; q < 8; ++q) {
            int m = msub * 8 + q;
            const float* xv = (q < 4) ? xgF[q & 3] : xgS[q & 3];
            float gi = xv[0], gf = xv[1], gz = xv[2], go = xv[3];
            if (k > 0) {
                const float* gr = gs + m * GST + j;
                gi += gr[0]; gf += gr[64]; gz += gr[128]; go += gr[192];
            }
            float iv = sigm(gi), fv = sigm(gf), zv = tanhf(gz), ov = sigm(go);
            cst[q] = fv * cst[q] + iv * zv;
            float h = ov * tanhf(cst[q]);
            __nv_bfloat16 hh, hl;
            split_bf(h, hh, hl);
            char* hp = (char*)(Hs + m * WST);
            *(__nv_bfloat16*)(hp + 2 * j)       = hh;
            *(__nv_bfloat16*)(hp + 128 + 2 * j) = hl;
            if (k == KNB - 1 && n0 + m < N_NODES)
                out[(size_t)(n0 + m) * 128 + j] = h;
        }

        // ---- prefetch next step, second half (covered by barrier + next MMA) ----
        if (k < KNB - 1) {
            #pragma unroll
            for (int q = 0; q < 4; ++q) {
                const float* xp = g_P + (size_t)idxs[(msub * 8 + q + 4) * KNB + k + 1] * GDIM + j;
                xgS[q][0] = xp[0]; xgS[q][1] = xp[64]; xgS[q][2] = xp[128]; xgS[q][3] = xp[192];
            }
            #pragma unroll
            for (int q = 0; q < 4; ++q)
                #pragma unroll
                for (int cc = 0; cc < 4; ++cc) xgF[q][cc] = xgN[q][cc];
        }
        __syncthreads();
    }

    // ---- backward direction: single cell from zero state ----
    #pragma unroll
    for (int q = 0; q < 8; ++q) {
        int m = msub * 8 + q, n = n0 + m;
        if (n < N_NODES) {
            const float* gb = g_Gb + (size_t)n * GDIM + j;
            float cb = sigm(gb[0]) * tanhf(gb[128]);
            float hb = sigm(gb[192]) * tanhf(cb);
            out[(size_t)n * 128 + HDIM + j] = hb;
        }
    }
}

// ============================================================================
extern "C" void kernel_launch(void* const* d_in, const int* in_sizes, int n_in,
                              void* d_out, int out_size) {
    const int*   nidx  = (const int*)  d_in[0];
    const float* E     = (const float*)d_in[1];
    const float* Wih_f = (const float*)d_in[2];
    const float* Whh_f = (const float*)d_in[3];
    const float* bih_f = (const float*)d_in[4];
    const float* bhh_f = (const float*)d_in[5];
    const float* Wih_b = (const float*)d_in[6];
    const float* Whh_b = (const float*)d_in[7];  // unused: h0 = 0
    const float* bih_b = (const float*)d_in[8];
    const float* bhh_b = (const float*)d_in[9];
    float* out = (float*)d_out;
    (void)Whh_b; (void)in_sizes; (void)n_in; (void)out_size;

    cudaFuncSetAttribute(proj_all,    cudaFuncAttributeMaxDynamicSharedMemorySize, TC_SMEM);
    cudaFuncSetAttribute(lstm_kernel, cudaFuncAttributeMaxDynamicSharedMemorySize, LSTM_SMEM);

    // 1) both projections in one launch: forward table -> g_P, backward gates -> g_Gb
    proj_all<<<dim3(4, NBF + NBT), 256, TC_SMEM>>>(
        E, Wih_f, bih_f, bhh_f, Wih_b, bih_b, bhh_b, nidx);
    // 2) forward recurrence (HMMA, conflict-free smem, full-step gather prefetch)
    lstm_kernel<<<(N_NODES + LNB - 1) / LNB, 256, LSTM_SMEM>>>(nidx, Whh_f, out);
}

// round 14
// speedup vs baseline: 1.0012x; 1.0012x over previous
#include <cuda_runtime.h>
#include <cuda_bf16.h>
#include <cstdint>

#define N_NODES 50000
#define KNB     10
#define VROWS   200000
#define FDIM    128
#define HDIM    64
#define GDIM    256   // 4*H

typedef unsigned long long ull;

// scratch: projected forward table and backward gates (device globals — no allocs)
__device__ float g_P [(size_t)VROWS  * GDIM];   // 204.8 MB
__device__ float g_Gb[(size_t)N_NODES * GDIM];  //  51.2 MB

// ---------------- helpers ----------------
static __device__ __forceinline__ float sigm(float x) {
    return 1.0f / (1.0f + __expf(-x));
}
static __device__ __forceinline__ float tanh_f(float x) {
    return 1.0f - 2.0f / (1.0f + __expf(2.0f * x));
}
static __device__ __forceinline__ unsigned pack2bf(__nv_bfloat16 a, __nv_bfloat16 b) {
    __nv_bfloat162 t(a, b);
    return *(unsigned*)&t;
}
// warp-level bf16 HMMA (arch-portable; compiles under compute_103 virtual)
static __device__ __forceinline__ void mma16816(float* c,
    uint32_t a0, uint32_t a1, uint32_t a2, uint32_t a3, uint32_t b0, uint32_t b1) {
    asm volatile(
        "mma.sync.aligned.m16n8k16.row.col.f32.bf16.bf16.f32 "
        "{%0,%1,%2,%3}, {%4,%5,%6,%7}, {%8,%9}, {%0,%1,%2,%3};"
        : "+f"(c[0]), "+f"(c[1]), "+f"(c[2]), "+f"(c[3])
        : "r"(a0), "r"(a1), "r"(a2), "r"(a3), "r"(b0), "r"(b1));
}
static __device__ __forceinline__ void split_bf(float f, __nv_bfloat16& h, __nv_bfloat16& l) {
    h = __float2bfloat16_rn(f);
    l = __float2bfloat16_rn(f - __bfloat162float(h));
}

// ============================================================================
// HMMA projection (R10 config — best measured, reverted from R11 merge):
// out[row, gbase+g] = sum_f src[row][f] * W[gbase+g][f] + b1[g]+b2[g]
// fp32 via 3-term bf16 split: Ah*Bh + Ah*Bl + Al*Bh (fp32 accumulators).
// CTA tile: 128 rows x 64 gates, K=128 (smem 105 KB -> 2 CTAs/SM).
// grid.x = gate quarter (fast axis) -> concurrent blocks share A via L2.
// ============================================================================
#define ROW_U32 68
#define TILE_A (128 * ROW_U32 * 4)
#define TILE_B (64  * ROW_U32 * 4)
#define OFF_IDX  0
#define OFF_BIAS 512
#define OFF_AH   1024
#define OFF_AL   (OFF_AH + TILE_A)
#define OFF_BH   (OFF_AL + TILE_A)
#define OFF_BL   (OFF_BH + TILE_B)
#define TC_SMEM  (OFF_BL + TILE_B)          // 105472

template<bool GATHER>
__global__ __launch_bounds__(256, 2) void proj_tc(
    const float* __restrict__ E, const float* __restrict__ W,
    const float* __restrict__ b1, const float* __restrict__ b2,
    const int* __restrict__ nidx, int nrows)
{
    extern __shared__ __align__(16) char smem[];
    int*      idxs = (int*)(smem + OFF_IDX);
    float*    bias = (float*)(smem + OFF_BIAS);
    uint32_t* Ah   = (uint32_t*)(smem + OFF_AH);
    uint32_t* Al   = (uint32_t*)(smem + OFF_AL);
    uint32_t* Bh   = (uint32_t*)(smem + OFF_BH);
    uint32_t* Bl   = (uint32_t*)(smem + OFF_BL);

    const int tid   = threadIdx.x;
    const int r0    = blockIdx.y * 128;
    const int gbase = blockIdx.x * 64;

    if (tid < 64) bias[tid] = b1[gbase + tid] + b2[gbase + tid];
    if (GATHER && tid < 128) {
        int n = r0 + tid; if (n >= nrows) n = nrows - 1;
        idxs[tid] = nidx[n * KNB + (KNB - 1)];
    }
    if (GATHER) __syncthreads();

    for (int u = tid; u < 64 * 16; u += 256) {
        int g = u >> 4, c8 = (u & 15) * 8;
        const float* src = W + (size_t)(gbase + g) * FDIM + c8;
        float4 v0 = *(const float4*)(src);
        float4 v1 = *(const float4*)(src + 4);
        float f[8] = {v0.x, v0.y, v0.z, v0.w, v1.x, v1.y, v1.z, v1.w};
        __nv_bfloat16 h[8], l[8];
        #pragma unroll
        for (int i = 0; i < 8; ++i) split_bf(f[i], h[i], l[i]);
        int du = g * ROW_U32 + (c8 >> 1);
        *(uint4*)&Bh[du] = make_uint4(pack2bf(h[0],h[1]), pack2bf(h[2],h[3]), pack2bf(h[4],h[5]), pack2bf(h[6],h[7]));
        *(uint4*)&Bl[du] = make_uint4(pack2bf(l[0],l[1]), pack2bf(l[2],l[3]), pack2bf(l[4],l[5]), pack2bf(l[6],l[7]));
    }
    for (int u = tid; u < 128 * 16; u += 256) {
        int r = u >> 4, c8 = (u & 15) * 8;
        size_t srow;
        if (GATHER) srow = (size_t)idxs[r];
        else { int rr = r0 + r; if (rr >= nrows) rr = nrows - 1; srow = (size_t)rr; }
        const float* src = E + srow * FDIM + c8;
        float4 v0 = *(const float4*)(src);
        float4 v1 = *(const float4*)(src + 4);
        float f[8] = {v0.x, v0.y, v0.z, v0.w, v1.x, v1.y, v1.z, v1.w};
        __nv_bfloat16 h[8], l[8];
        #pragma unroll
        for (int i = 0; i < 8; ++i) split_bf(f[i], h[i], l[i]);
        int du = r * ROW_U32 + (c8 >> 1);
        *(uint4*)&Ah[du] = make_uint4(pack2bf(h[0],h[1]), pack2bf(h[2],h[3]), pack2bf(h[4],h[5]), pack2bf(h[6],h[7]));
        *(uint4*)&Al[du] = make_uint4(pack2bf(l[0],l[1]), pack2bf(l[2],l[3]), pack2bf(l[4],l[5]), pack2bf(l[6],l[7]));
    }
    __syncthreads();

    const int wid  = tid >> 5, lane = tid & 31;
    const int wm   = wid & 3, wn = wid >> 2;
    const int g    = lane >> 2, t = lane & 3;

    float c[2][4][4];
    #pragma unroll
    for (int mi = 0; mi < 2; ++mi)
        #pragma unroll
        for (int ni = 0; ni < 4; ++ni)
            #pragma unroll
            for (int q = 0; q < 4; ++q) c[mi][ni][q] = 0.f;

    const uint32_t* Abase[3] = {Ah, Ah, Al};
    const uint32_t* Bbase[3] = {Bh, Bl, Bh};
    #pragma unroll
    for (int term = 0; term < 3; ++term) {
        const uint32_t* As = Abase[term];
        const uint32_t* Bs = Bbase[term];
        #pragma unroll
        for (int ks = 0; ks < 8; ++ks) {
            const int kc = ks * 8;
            uint32_t a[2][4];
            #pragma unroll
            for (int mi = 0; mi < 2; ++mi) {
                const uint32_t* ar = As + (wm * 32 + mi * 16 + g) * ROW_U32;
                a[mi][0] = ar[kc + t];
                a[mi][1] = ar[8 * ROW_U32 + kc + t];
                a[mi][2] = ar[kc + 4 + t];
                a[mi][3] = ar[8 * ROW_U32 + kc + 4 + t];
            }
            #pragma unroll
            for (int ni = 0; ni < 4; ++ni) {
                const uint32_t* br = Bs + (wn * 32 + ni * 8 + g) * ROW_U32;
                uint32_t b0 = br[kc + t];
                uint32_t b1 = br[kc + 4 + t];
                mma16816(c[0][ni], a[0][0], a[0][1], a[0][2], a[0][3], b0, b1);
                mma16816(c[1][ni], a[1][0], a[1][1], a[1][2], a[1][3], b0, b1);
            }
        }
    }

    float* outp = GATHER ? g_Gb : g_P;
    #pragma unroll
    for (int mi = 0; mi < 2; ++mi) {
        int row0 = r0 + wm * 32 + mi * 16 + g;
        #pragma unroll
        for (int ni = 0; ni < 4; ++ni) {
            int lc  = wn * 32 + ni * 8 + 2 * t;
            float bx = bias[lc], by = bias[lc + 1];
            if (row0 < nrows)
                *(float2*)&outp[(size_t)row0 * GDIM + gbase + lc] =
                    make_float2(c[mi][ni][0] + bx, c[mi][ni][1] + by);
            if (row0 + 8 < nrows)
                *(float2*)&outp[(size_t)(row0 + 8) * GDIM + gbase + lc] =
                    make_float2(c[mi][ni][2] + bx, c[mi][ni][3] + by);
        }
    }
}

// ============================================================================
// Fused-ownership HMMA recurrence: 32 nodes/block, 256 threads (8 warps).
// Warp (wm, wn): node rows wm*16..+15, hidden cols wn*16..+15, ALL 4 gate
// groups (B rows gg*64 + wn*16 + jj*8). Each thread's 32 accumulators are the
// complete (i,f,g,o) quadruples for its 8 cells -> cell update in registers,
// no gate staging, ONE barrier per step. H double-buffered (bf16 hi/lo,
// stride-65 rows) so cell(k) writes can't race other warps' MMA(k) reads.
// g_P gathers = per-thread float2 loads issued under the MMA's cover.
// smem 84.5 KB -> 2 CTAs/SM.
// ============================================================================
#define LNB 32
#define WST 65                              // u32 row stride: hi[0..31] lo[32..63] pad 1
#define L_W  0                              // 256*65 = 16640 u32
#define L_H0 (L_W + 256 * WST)              // 32*65 = 2080
#define L_H1 (L_H0 + LNB * WST)             // 2080
#define L_IX (L_H1 + LNB * WST)             // 320
#define LSTM_SMEM ((L_IX + LNB * KNB) * 4)  // 84480 bytes

__global__ __launch_bounds__(256, 2) void lstm_kernel(
    const int* __restrict__ nidx, const float* __restrict__ Whh,
    float* __restrict__ out)
{
    extern __shared__ __align__(16) char smraw[];
    uint32_t* sm   = (uint32_t*)smraw;
    uint32_t* Ws   = sm + L_W;
    int*      idxs = (int*)(sm + L_IX);
    uint32_t* Hbuf0 = sm + L_H0;
    uint32_t* Hbuf1 = sm + L_H1;

    const int tid  = threadIdx.x;
    const int wid  = tid >> 5, lane = tid & 31;
    const int n0   = blockIdx.x * LNB;

    // ---- prologue: indices (grid-stride, 320 entries) ----
    for (int u = tid; u < LNB * KNB; u += 256) {
        int m = u / KNB, kk = u % KNB;
        int n = n0 + m; if (n >= N_NODES) n = N_NODES - 1;
        idxs[m * KNB + kk] = nidx[n * KNB + kk];
    }
    // ---- Whh hi/lo split into stride-65 rows (thread = gate row; u32 stores) ----
    {
        const float* wr = Whh + tid * HDIM;
        uint32_t* wrow = Ws + tid * WST;
        #pragma unroll
        for (int i = 0; i < 16; ++i) {
            float4 v = *(const float4*)(wr + i * 4);
            __nv_bfloat16 h0,l0,h1,l1,h2,l2,h3,l3;
            split_bf(v.x,h0,l0); split_bf(v.y,h1,l1);
            split_bf(v.z,h2,l2); split_bf(v.w,h3,l3);
            wrow[2*i]          = pack2bf(h0,h1);
            wrow[2*i + 1]      = pack2bf(h2,h3);
            wrow[32 + 2*i]     = pack2bf(l0,l1);
            wrow[32 + 2*i + 1] = pack2bf(l2,l3);
        }
    }
    __syncthreads();

    const int wm = wid >> 2, wn = wid & 3;    // wm: node half, wn: hidden-col 16-slice
    const int g  = lane >> 2, t = lane & 3;
    const int r0 = wm * 16 + g;               // thread's node rows: r0, r0+8
    const int jc = wn * 16 + 2 * t;           // hidden col base; jj adds 8

    float cst[2][2][2];                       // [rr][jj][cc]
    #pragma unroll
    for (int rr = 0; rr < 2; ++rr)
        #pragma unroll
        for (int jj = 0; jj < 2; ++jj)
            { cst[rr][jj][0] = 0.f; cst[rr][jj][1] = 0.f; }

    #pragma unroll 1
    for (int k = 0; k < KNB; ++k) {
        uint32_t*       Hw = (k & 1) ? Hbuf1 : Hbuf0;   // write buf (state k)
        const uint32_t* Hr = (k & 1) ? Hbuf0 : Hbuf1;   // read buf (state k-1)

        // prefetch x for node row r0 (covered by the MMA below)
        float2 xr[2][4][2];                   // [rr][gg][jj]
        {
            const float* p = g_P + (size_t)idxs[r0 * KNB + k] * GDIM;
            #pragma unroll
            for (int gg = 0; gg < 4; ++gg)
                #pragma unroll
                for (int jj = 0; jj < 2; ++jj)
                    xr[0][gg][jj] = *(const float2*)(p + gg * 64 + jc + jj * 8);
        }

        float acc[4][2][4];
        #pragma unroll
        for (int gg = 0; gg < 4; ++gg)
            #pragma unroll
            for (int jj = 0; jj < 2; ++jj)
                #pragma unroll
                for (int q = 0; q < 4; ++q) acc[gg][jj][q] = 0.f;

        if (k > 0) {
            uint32_t ah[4][4], al[4][4];
            const uint32_t* ar = Hr + r0 * WST;
            #pragma unroll
            for (int ks = 0; ks < 4; ++ks) {
                const int kc = ks * 8;
                ah[ks][0] = ar[kc + t];              ah[ks][1] = ar[8 * WST + kc + t];
                ah[ks][2] = ar[kc + 4 + t];          ah[ks][3] = ar[8 * WST + kc + 4 + t];
                al[ks][0] = ar[32 + kc + t];         al[ks][1] = ar[8 * WST + 32 + kc + t];
                al[ks][2] = ar[32 + kc + 4 + t];     al[ks][3] = ar[8 * WST + 32 + kc + 4 + t];
            }
            #pragma unroll
            for (int gg = 0; gg < 4; ++gg)
                #pragma unroll
                for (int jj = 0; jj < 2; ++jj) {
                    const uint32_t* br = Ws + (gg * 64 + wn * 16 + jj * 8 + g) * WST;
                    #pragma unroll
                    for (int ks = 0; ks < 4; ++ks) {
                        const int kc = ks * 8;
                        uint32_t bh0 = br[kc + t],      bh1 = br[kc + 4 + t];
                        uint32_t bl0 = br[32 + kc + t], bl1 = br[32 + kc + 4 + t];
                        mma16816(acc[gg][jj], ah[ks][0], ah[ks][1], ah[ks][2], ah[ks][3], bh0, bh1);
                        mma16816(acc[gg][jj], ah[ks][0], ah[ks][1], ah[ks][2], ah[ks][3], bl0, bl1);
                        mma16816(acc[gg][jj], al[ks][0], al[ks][1], al[ks][2], al[ks][3], bh0, bh1);
                    }
                }
        }

        // prefetch x for node row r0+8 (covered by cell work on rr=0)
        {
            const float* p = g_P + (size_t)idxs[(r0 + 8) * KNB + k] * GDIM;
            #pragma unroll
            for (int gg = 0; gg < 4; ++gg)
                #pragma unroll
                for (int jj = 0; jj < 2; ++jj)
                    xr[1][gg][jj] = *(const float2*)(p + gg * 64 + jc + jj * 8);
        }

        // cell update: 8 cells per thread, entirely in registers
        #pragma unroll
        for (int rr = 0; rr < 2; ++rr) {
            const int r = r0 + rr * 8;
            #pragma unroll
            for (int jj = 0; jj < 2; ++jj) {
                float h2[2];
                #pragma unroll
                for (int cc = 0; cc < 2; ++cc) {
                    const int q = rr * 2 + cc;
                    float xi = cc ? xr[rr][0][jj].y : xr[rr][0][jj].x;
                    float xf = cc ? xr[rr][1][jj].y : xr[rr][1][jj].x;
                    float xz = cc ? xr[rr][2][jj].y : xr[rr][2][jj].x;
                    float xo = cc ? xr[rr][3][jj].y : xr[rr][3][jj].x;
                    float iv = sigm(acc[0][jj][q] + xi);
                    float fv = sigm(acc[1][jj][q] + xf);
                    float zv = tanh_f(acc[2][jj][q] + xz);
                    float ov = sigm(acc[3][jj][q] + xo);
                    float cn = fv * cst[rr][jj][cc] + iv * zv;
                    cst[rr][jj][cc] = cn;
                    h2[cc] = ov * tanh_f(cn);
                }
                __nv_bfloat16 h0h, h0l, h1h, h1l;
                split_bf(h2[0], h0h, h0l);
                split_bf(h2[1], h1h, h1l);
                const int wc = wn * 8 + jj * 4 + t;
                Hw[r * WST + wc]      = pack2bf(h0h, h1h);
                Hw[r * WST + 32 + wc] = pack2bf(h0l, h1l);
                if (k == KNB - 1 && n0 + r < N_NODES)
                    *(float2*)&out[(size_t)(n0 + r) * 128 + jc + jj * 8] =
                        make_float2(h2[0], h2[1]);
            }
        }
        __syncthreads();
    }

    // ---- backward direction: single cell from zero state ----
    #pragma unroll
    for (int rr = 0; rr < 2; ++rr) {
        const int r = r0 + rr * 8, n = n0 + r;
        if (n < N_NODES) {
            const float* gb = g_Gb + (size_t)n * GDIM;
            #pragma unroll
            for (int jj = 0; jj < 2; ++jj) {
                const int col = jc + jj * 8;
                float2 xi = *(const float2*)(gb + col);
                float2 xz = *(const float2*)(gb + col + 128);
                float2 xo = *(const float2*)(gb + col + 192);
                float c0 = sigm(xi.x) * tanh_f(xz.x);
                float c1 = sigm(xi.y) * tanh_f(xz.y);
                float h0 = sigm(xo.x) * tanh_f(c0);
                float h1 = sigm(xo.y) * tanh_f(c1);
                *(float2*)&out[(size_t)n * 128 + HDIM + col] = make_float2(h0, h1);
            }
        }
    }
}

// ============================================================================
extern "C" void kernel_launch(void* const* d_in, const int* in_sizes, int n_in,
                              void* d_out, int out_size) {
    const int*   nidx  = (const int*)  d_in[0];
    const float* E     = (const float*)d_in[1];
    const float* Wih_f = (const float*)d_in[2];
    const float* Whh_f = (const float*)d_in[3];
    const float* bih_f = (const float*)d_in[4];
    const float* bhh_f = (const float*)d_in[5];
    const float* Wih_b = (const float*)d_in[6];
    const float* Whh_b = (const float*)d_in[7];  // unused: h0 = 0
    const float* bih_b = (const float*)d_in[8];
    const float* bhh_b = (const float*)d_in[9];
    float* out = (float*)d_out;
    (void)Whh_b; (void)in_sizes; (void)n_in; (void)out_size;

    cudaFuncSetAttribute(proj_tc<false>, cudaFuncAttributeMaxDynamicSharedMemorySize, TC_SMEM);
    cudaFuncSetAttribute(proj_tc<true>,  cudaFuncAttributeMaxDynamicSharedMemorySize, TC_SMEM);
    cudaFuncSetAttribute(lstm_kernel,    cudaFuncAttributeMaxDynamicSharedMemorySize, LSTM_SMEM);

    // 1) forward projected table: P = E @ Wih_f^T + (bih_f + bhh_f)   [HMMA bf16 x3]
    proj_tc<false><<<dim3(4, (VROWS + 127) / 128), 256, TC_SMEM>>>(
        E, Wih_f, bih_f, bhh_f, nullptr, VROWS);
    // 2) backward gates: Gb[n] = Wih_b @ E[idx[n][K-1]] + (bih_b + bhh_b)
    proj_tc<true><<<dim3(4, (N_NODES + 127) / 128), 256, TC_SMEM>>>(
        E, Wih_b, bih_b, bhh_b, nidx, N_NODES);
    // 3) forward recurrence (fused-ownership HMMA, 1 barrier/step) + both halves
    lstm_kernel<<<(N_NODES + LNB - 1) / LNB, 256, LSTM_SMEM>>>(nidx, Whh_f, out);
}

// round 15
// speedup vs baseline: 1.2282x; 1.2267x over previous
#include <cuda_runtime.h>
#include <cuda_bf16.h>
#include <cstdint>

#define N_NODES 50000
#define KNB     10
#define VROWS   200000
#define FDIM    128
#define HDIM    64
#define GDIM    256   // 4*H

typedef unsigned long long ull;

// scratch: projected forward table and backward gates (device globals — no allocs)
__device__ float g_P [(size_t)VROWS  * GDIM];   // 204.8 MB
__device__ float g_Gb[(size_t)N_NODES * GDIM];  //  51.2 MB

// ---------------- helpers ----------------
static __device__ __forceinline__ float sigm(float x) {
    return 1.0f / (1.0f + __expf(-x));
}
static __device__ __forceinline__ float tanh_f(float x) {
    return 1.0f - 2.0f / (1.0f + __expf(2.0f * x));
}
static __device__ __forceinline__ unsigned pack2bf(__nv_bfloat16 a, __nv_bfloat16 b) {
    __nv_bfloat162 t(a, b);
    return *(unsigned*)&t;
}
// warp-level bf16 HMMA (arch-portable; compiles under compute_103 virtual)
static __device__ __forceinline__ void mma16816(float* c,
    uint32_t a0, uint32_t a1, uint32_t a2, uint32_t a3, uint32_t b0, uint32_t b1) {
    asm volatile(
        "mma.sync.aligned.m16n8k16.row.col.f32.bf16.bf16.f32 "
        "{%0,%1,%2,%3}, {%4,%5,%6,%7}, {%8,%9}, {%0,%1,%2,%3};"
        : "+f"(c[0]), "+f"(c[1]), "+f"(c[2]), "+f"(c[3])
        : "r"(a0), "r"(a1), "r"(a2), "r"(a3), "r"(b0), "r"(b1));
}
static __device__ __forceinline__ void split_bf(float f, __nv_bfloat16& h, __nv_bfloat16& l) {
    h = __float2bfloat16_rn(f);
    l = __float2bfloat16_rn(f - __bfloat162float(h));
}

// ============================================================================
// HMMA projection (R10 config — best measured):
// out[row, gbase+g] = sum_f src[row][f] * W[gbase+g][f] + b1[g]+b2[g]
// fp32 via 3-term bf16 split: Ah*Bh + Ah*Bl + Al*Bh (fp32 accumulators).
// CTA tile: 128 rows x 64 gates, K=128 (smem 105 KB -> 2 CTAs/SM).
// grid.x = gate quarter (fast axis) -> concurrent blocks share A via L2.
// ============================================================================
#define ROW_U32 68
#define TILE_A (128 * ROW_U32 * 4)
#define TILE_B (64  * ROW_U32 * 4)
#define OFF_IDX  0
#define OFF_BIAS 512
#define OFF_AH   1024
#define OFF_AL   (OFF_AH + TILE_A)
#define OFF_BH   (OFF_AL + TILE_A)
#define OFF_BL   (OFF_BH + TILE_B)
#define TC_SMEM  (OFF_BL + TILE_B)          // 105472

template<bool GATHER>
__global__ __launch_bounds__(256, 2) void proj_tc(
    const float* __restrict__ E, const float* __restrict__ W,
    const float* __restrict__ b1, const float* __restrict__ b2,
    const int* __restrict__ nidx, int nrows)
{
    extern __shared__ __align__(16) char smem[];
    int*      idxs = (int*)(smem + OFF_IDX);
    float*    bias = (float*)(smem + OFF_BIAS);
    uint32_t* Ah   = (uint32_t*)(smem + OFF_AH);
    uint32_t* Al   = (uint32_t*)(smem + OFF_AL);
    uint32_t* Bh   = (uint32_t*)(smem + OFF_BH);
    uint32_t* Bl   = (uint32_t*)(smem + OFF_BL);

    const int tid   = threadIdx.x;
    const int r0    = blockIdx.y * 128;
    const int gbase = blockIdx.x * 64;

    if (tid < 64) bias[tid] = b1[gbase + tid] + b2[gbase + tid];
    if (GATHER && tid < 128) {
        int n = r0 + tid; if (n >= nrows) n = nrows - 1;
        idxs[tid] = nidx[n * KNB + (KNB - 1)];
    }
    if (GATHER) __syncthreads();

    for (int u = tid; u < 64 * 16; u += 256) {
        int g = u >> 4, c8 = (u & 15) * 8;
        const float* src = W + (size_t)(gbase + g) * FDIM + c8;
        float4 v0 = *(const float4*)(src);
        float4 v1 = *(const float4*)(src + 4);
        float f[8] = {v0.x, v0.y, v0.z, v0.w, v1.x, v1.y, v1.z, v1.w};
        __nv_bfloat16 h[8], l[8];
        #pragma unroll
        for (int i = 0; i < 8; ++i) split_bf(f[i], h[i], l[i]);
        int du = g * ROW_U32 + (c8 >> 1);
        *(uint4*)&Bh[du] = make_uint4(pack2bf(h[0],h[1]), pack2bf(h[2],h[3]), pack2bf(h[4],h[5]), pack2bf(h[6],h[7]));
        *(uint4*)&Bl[du] = make_uint4(pack2bf(l[0],l[1]), pack2bf(l[2],l[3]), pack2bf(l[4],l[5]), pack2bf(l[6],l[7]));
    }
    for (int u = tid; u < 128 * 16; u += 256) {
        int r = u >> 4, c8 = (u & 15) * 8;
        size_t srow;
        if (GATHER) srow = (size_t)idxs[r];
        else { int rr = r0 + r; if (rr >= nrows) rr = nrows - 1; srow = (size_t)rr; }
        const float* src = E + srow * FDIM + c8;
        float4 v0 = *(const float4*)(src);
        float4 v1 = *(const float4*)(src + 4);
        float f[8] = {v0.x, v0.y, v0.z, v0.w, v1.x, v1.y, v1.z, v1.w};
        __nv_bfloat16 h[8], l[8];
        #pragma unroll
        for (int i = 0; i < 8; ++i) split_bf(f[i], h[i], l[i]);
        int du = r * ROW_U32 + (c8 >> 1);
        *(uint4*)&Ah[du] = make_uint4(pack2bf(h[0],h[1]), pack2bf(h[2],h[3]), pack2bf(h[4],h[5]), pack2bf(h[6],h[7]));
        *(uint4*)&Al[du] = make_uint4(pack2bf(l[0],l[1]), pack2bf(l[2],l[3]), pack2bf(l[4],l[5]), pack2bf(l[6],l[7]));
    }
    __syncthreads();

    const int wid  = tid >> 5, lane = tid & 31;
    const int wm   = wid & 3, wn = wid >> 2;
    const int g    = lane >> 2, t = lane & 3;

    float c[2][4][4];
    #pragma unroll
    for (int mi = 0; mi < 2; ++mi)
        #pragma unroll
        for (int ni = 0; ni < 4; ++ni)
            #pragma unroll
            for (int q = 0; q < 4; ++q) c[mi][ni][q] = 0.f;

    const uint32_t* Abase[3] = {Ah, Ah, Al};
    const uint32_t* Bbase[3] = {Bh, Bl, Bh};
    #pragma unroll
    for (int term = 0; term < 3; ++term) {
        const uint32_t* As = Abase[term];
        const uint32_t* Bs = Bbase[term];
        #pragma unroll
        for (int ks = 0; ks < 8; ++ks) {
            const int kc = ks * 8;
            uint32_t a[2][4];
            #pragma unroll
            for (int mi = 0; mi < 2; ++mi) {
                const uint32_t* ar = As + (wm * 32 + mi * 16 + g) * ROW_U32;
                a[mi][0] = ar[kc + t];
                a[mi][1] = ar[8 * ROW_U32 + kc + t];
                a[mi][2] = ar[kc + 4 + t];
                a[mi][3] = ar[8 * ROW_U32 + kc + 4 + t];
            }
            #pragma unroll
            for (int ni = 0; ni < 4; ++ni) {
                const uint32_t* br = Bs + (wn * 32 + ni * 8 + g) * ROW_U32;
                uint32_t b0 = br[kc + t];
                uint32_t b1 = br[kc + 4 + t];
                mma16816(c[0][ni], a[0][0], a[0][1], a[0][2], a[0][3], b0, b1);
                mma16816(c[1][ni], a[1][0], a[1][1], a[1][2], a[1][3], b0, b1);
            }
        }
    }

    float* outp = GATHER ? g_Gb : g_P;
    #pragma unroll
    for (int mi = 0; mi < 2; ++mi) {
        int row0 = r0 + wm * 32 + mi * 16 + g;
        #pragma unroll
        for (int ni = 0; ni < 4; ++ni) {
            int lc  = wn * 32 + ni * 8 + 2 * t;
            float bx = bias[lc], by = bias[lc + 1];
            if (row0 < nrows)
                *(float2*)&outp[(size_t)row0 * GDIM + gbase + lc] =
                    make_float2(c[mi][ni][0] + bx, c[mi][ni][1] + by);
            if (row0 + 8 < nrows)
                *(float2*)&outp[(size_t)(row0 + 8) * GDIM + gbase + lc] =
                    make_float2(c[mi][ni][2] + bx, c[mi][ni][3] + by);
        }
    }
}

// ============================================================================
// Fused-ownership HMMA recurrence (R13 design, WST fixed 65 -> 68):
// 32 nodes/block, 256 threads. Warp (wm, wn): node rows wm*16..+15, hidden
// cols wn*16..+15, ALL 4 gate groups. Thread's 32 accumulators = complete
// (i,f,g,o) quadruples for its 8 cells -> cell update in registers, no gate
// staging, ONE barrier per step. H double-buffered.
// WST=68 -> every fragment LDS has bank (4g + kc + t): conflict-free
// (WST=65 gave (g + kc + t): 4-way conflicts — the R13 regression).
// smem 88.3 KB -> 2 CTAs/SM.
// ============================================================================
#define LNB 32
#define WST 68                              // u32 row stride: hi[0..31] lo[32..63] pad 4
#define L_W  0                              // 256*68 = 17408 u32
#define L_H0 (L_W + 256 * WST)              // 32*68 = 2176
#define L_H1 (L_H0 + LNB * WST)             // 2176
#define L_IX (L_H1 + LNB * WST)             // 320
#define LSTM_SMEM ((L_IX + LNB * KNB) * 4)  // 88320 bytes

__global__ __launch_bounds__(256, 2) void lstm_kernel(
    const int* __restrict__ nidx, const float* __restrict__ Whh,
    float* __restrict__ out)
{
    extern __shared__ __align__(16) char smraw[];
    uint32_t* sm   = (uint32_t*)smraw;
    uint32_t* Ws   = sm + L_W;
    int*      idxs = (int*)(sm + L_IX);
    uint32_t* Hbuf0 = sm + L_H0;
    uint32_t* Hbuf1 = sm + L_H1;

    const int tid  = threadIdx.x;
    const int wid  = tid >> 5, lane = tid & 31;
    const int n0   = blockIdx.x * LNB;

    // ---- prologue: indices (grid-stride, 320 entries) ----
    for (int u = tid; u < LNB * KNB; u += 256) {
        int m = u / KNB, kk = u % KNB;
        int n = n0 + m; if (n >= N_NODES) n = N_NODES - 1;
        idxs[m * KNB + kk] = nidx[n * KNB + kk];
    }
    // ---- Whh hi/lo split into stride-68 rows (thread = gate row) ----
    {
        const float* wr = Whh + tid * HDIM;
        uint32_t* wrow = Ws + tid * WST;
        #pragma unroll
        for (int i = 0; i < 16; ++i) {
            float4 v = *(const float4*)(wr + i * 4);
            __nv_bfloat16 h0,l0,h1,l1,h2,l2,h3,l3;
            split_bf(v.x,h0,l0); split_bf(v.y,h1,l1);
            split_bf(v.z,h2,l2); split_bf(v.w,h3,l3);
            wrow[2*i]          = pack2bf(h0,h1);
            wrow[2*i + 1]      = pack2bf(h2,h3);
            wrow[32 + 2*i]     = pack2bf(l0,l1);
            wrow[32 + 2*i + 1] = pack2bf(l2,l3);
        }
    }
    __syncthreads();

    const int wm = wid >> 2, wn = wid & 3;    // wm: node half, wn: hidden-col 16-slice
    const int g  = lane >> 2, t = lane & 3;
    const int r0 = wm * 16 + g;               // thread's node rows: r0, r0+8
    const int jc = wn * 16 + 2 * t;           // hidden col base; jj adds 8

    float cst[2][2][2];                       // [rr][jj][cc]
    #pragma unroll
    for (int rr = 0; rr < 2; ++rr)
        #pragma unroll
        for (int jj = 0; jj < 2; ++jj)
            { cst[rr][jj][0] = 0.f; cst[rr][jj][1] = 0.f; }

    #pragma unroll 1
    for (int k = 0; k < KNB; ++k) {
        uint32_t*       Hw = (k & 1) ? Hbuf1 : Hbuf0;   // write buf (state k)
        const uint32_t* Hr = (k & 1) ? Hbuf0 : Hbuf1;   // read buf (state k-1)

        // prefetch x for node row r0 (covered by the MMA below)
        float2 xr[2][4][2];                   // [rr][gg][jj]
        {
            const float* p = g_P + (size_t)idxs[r0 * KNB + k] * GDIM;
            #pragma unroll
            for (int gg = 0; gg < 4; ++gg)
                #pragma unroll
                for (int jj = 0; jj < 2; ++jj)
                    xr[0][gg][jj] = *(const float2*)(p + gg * 64 + jc + jj * 8);
        }

        float acc[4][2][4];
        #pragma unroll
        for (int gg = 0; gg < 4; ++gg)
            #pragma unroll
            for (int jj = 0; jj < 2; ++jj)
                #pragma unroll
                for (int q = 0; q < 4; ++q) acc[gg][jj][q] = 0.f;

        if (k > 0) {
            uint32_t ah[4][4], al[4][4];
            const uint32_t* ar = Hr + r0 * WST;
            #pragma unroll
            for (int ks = 0; ks < 4; ++ks) {
                const int kc = ks * 8;
                ah[ks][0] = ar[kc + t];              ah[ks][1] = ar[8 * WST + kc + t];
                ah[ks][2] = ar[kc + 4 + t];          ah[ks][3] = ar[8 * WST + kc + 4 + t];
                al[ks][0] = ar[32 + kc + t];         al[ks][1] = ar[8 * WST + 32 + kc + t];
                al[ks][2] = ar[32 + kc + 4 + t];     al[ks][3] = ar[8 * WST + 32 + kc + 4 + t];
            }
            #pragma unroll
            for (int gg = 0; gg < 4; ++gg)
                #pragma unroll
                for (int jj = 0; jj < 2; ++jj) {
                    const uint32_t* br = Ws + (gg * 64 + wn * 16 + jj * 8 + g) * WST;
                    #pragma unroll
                    for (int ks = 0; ks < 4; ++ks) {
                        const int kc = ks * 8;
                        uint32_t bh0 = br[kc + t],      bh1 = br[kc + 4 + t];
                        uint32_t bl0 = br[32 + kc + t], bl1 = br[32 + kc + 4 + t];
                        mma16816(acc[gg][jj], ah[ks][0], ah[ks][1], ah[ks][2], ah[ks][3], bh0, bh1);
                        mma16816(acc[gg][jj], ah[ks][0], ah[ks][1], ah[ks][2], ah[ks][3], bl0, bl1);
                        mma16816(acc[gg][jj], al[ks][0], al[ks][1], al[ks][2], al[ks][3], bh0, bh1);
                    }
                }
        }

        // prefetch x for node row r0+8 (covered by cell work on rr=0)
        {
            const float* p = g_P + (size_t)idxs[(r0 + 8) * KNB + k] * GDIM;
            #pragma unroll
            for (int gg = 0; gg < 4; ++gg)
                #pragma unroll
                for (int jj = 0; jj < 2; ++jj)
                    xr[1][gg][jj] = *(const float2*)(p + gg * 64 + jc + jj * 8);
        }

        // cell update: 8 cells per thread, entirely in registers
        #pragma unroll
        for (int rr = 0; rr < 2; ++rr) {
            const int r = r0 + rr * 8;
            #pragma unroll
            for (int jj = 0; jj < 2; ++jj) {
                float h2[2];
                #pragma unroll
                for (int cc = 0; cc < 2; ++cc) {
                    const int q = rr * 2 + cc;
                    float xi = cc ? xr[rr][0][jj].y : xr[rr][0][jj].x;
                    float xf = cc ? xr[rr][1][jj].y : xr[rr][1][jj].x;
                    float xz = cc ? xr[rr][2][jj].y : xr[rr][2][jj].x;
                    float xo = cc ? xr[rr][3][jj].y : xr[rr][3][jj].x;
                    float iv = sigm(acc[0][jj][q] + xi);
                    float fv = sigm(acc[1][jj][q] + xf);
                    float zv = tanh_f(acc[2][jj][q] + xz);
                    float ov = sigm(acc[3][jj][q] + xo);
                    float cn = fv * cst[rr][jj][cc] + iv * zv;
                    cst[rr][jj][cc] = cn;
                    h2[cc] = ov * tanh_f(cn);
                }
                __nv_bfloat16 h0h, h0l, h1h, h1l;
                split_bf(h2[0], h0h, h0l);
                split_bf(h2[1], h1h, h1l);
                const int wc = wn * 8 + jj * 4 + t;
                Hw[r * WST + wc]      = pack2bf(h0h, h1h);
                Hw[r * WST + 32 + wc] = pack2bf(h0l, h1l);
                if (k == KNB - 1 && n0 + r < N_NODES)
                    *(float2*)&out[(size_t)(n0 + r) * 128 + jc + jj * 8] =
                        make_float2(h2[0], h2[1]);
            }
        }
        __syncthreads();
    }

    // ---- backward direction: single cell from zero state ----
    #pragma unroll
    for (int rr = 0; rr < 2; ++rr) {
        const int r = r0 + rr * 8, n = n0 + r;
        if (n < N_NODES) {
            const float* gb = g_Gb + (size_t)n * GDIM;
            #pragma unroll
            for (int jj = 0; jj < 2; ++jj) {
                const int col = jc + jj * 8;
                float2 xi = *(const float2*)(gb + col);
                float2 xz = *(const float2*)(gb + col + 128);
                float2 xo = *(const float2*)(gb + col + 192);
                float c0 = sigm(xi.x) * tanh_f(xz.x);
                float c1 = sigm(xi.y) * tanh_f(xz.y);
                float h0 = sigm(xo.x) * tanh_f(c0);
                float h1 = sigm(xo.y) * tanh_f(c1);
                *(float2*)&out[(size_t)n * 128 + HDIM + col] = make_float2(h0, h1);
            }
        }
    }
}

// ============================================================================
extern "C" void kernel_launch(void* const* d_in, const int* in_sizes, int n_in,
                              void* d_out, int out_size) {
    const int*   nidx  = (const int*)  d_in[0];
    const float* E     = (const float*)d_in[1];
    const float* Wih_f = (const float*)d_in[2];
    const float* Whh_f = (const float*)d_in[3];
    const float* bih_f = (const float*)d_in[4];
    const float* bhh_f = (const float*)d_in[5];
    const float* Wih_b = (const float*)d_in[6];
    const float* Whh_b = (const float*)d_in[7];  // unused: h0 = 0
    const float* bih_b = (const float*)d_in[8];
    const float* bhh_b = (const float*)d_in[9];
    float* out = (float*)d_out;
    (void)Whh_b; (void)in_sizes; (void)n_in; (void)out_size;

    cudaFuncSetAttribute(proj_tc<false>, cudaFuncAttributeMaxDynamicSharedMemorySize, TC_SMEM);
    cudaFuncSetAttribute(proj_tc<true>,  cudaFuncAttributeMaxDynamicSharedMemorySize, TC_SMEM);
    cudaFuncSetAttribute(lstm_kernel,    cudaFuncAttributeMaxDynamicSharedMemorySize, LSTM_SMEM);

    // 1) forward projected table: P = E @ Wih_f^T + (bih_f + bhh_f)   [HMMA bf16 x3]
    proj_tc<false><<<dim3(4, (VROWS + 127) / 128), 256, TC_SMEM>>>(
        E, Wih_f, bih_f, bhh_f, nullptr, VROWS);
    // 2) backward gates: Gb[n] = Wih_b @ E[idx[n][K-1]] + (bih_b + bhh_b)
    proj_tc<true><<<dim3(4, (N_NODES + 127) / 128), 256, TC_SMEM>>>(
        E, Wih_b, bih_b, bhh_b, nidx, N_NODES);
    // 3) forward recurrence (fused-ownership HMMA, conflict-free WST=68)
    lstm_kernel<<<(N_NODES + LNB - 1) / LNB, 256, LSTM_SMEM>>>(nidx, Whh_f, out);
}